// round 3
// baseline (speedup 1.0000x reference)
#include <cuda_runtime.h>

// Problem constants
#define B_  256
#define C_  64
#define T_  406
#define D_  10
#define TD  4060          // T*D
#define KP  4608          // [0,4060)=m*wn*x | [4060,4466)=mask | rest 0
#define SPLITK 9
#define KCH 512           // KP / SPLITK

// Output offsets (floats): output_seq, input_seq, loss, indices, label, mask, proto_count
#define O_OUT  0
#define O_IN   1039360
#define O_LOSS 2078720
#define O_IDX  2095104
#define O_LAB  2095360
#define O_MASK 2095616
#define O_PC   2199552

// Static scratch
__device__ __align__(16) float g_Y[B_ * KP];          // 4.72 MB
__device__ __align__(16) float g_P[C_ * KP];          // 1.18 MB
__device__ float g_part[SPLITK * B_ * C_];            // 0.59 MB
__device__ float g_S1[B_];
__device__ unsigned g_cnt[32];                         // per (x,y) tile counters

// ---------------------------------------------------------------------------
// Kernel 1: fused prep. Every block redundantly computes softplus(w) into
// smem (deterministic identical reduction order in every block -> identical
// inv everywhere). Then:
//   blocks [0, 64):    P' row c = [p | -0.5*inv*Q | 0]
//   blocks [64, 320):  Y row b = [m*sp*inv*x | m | 0], S1[b], pass-through
//                      copies, prototype gather, indices/label
//   block 320:         proto_count
// ---------------------------------------------------------------------------
__global__ void __launch_bounds__(256) prep_kernel(
    const float* __restrict__ x, const int* __restrict__ label,
    const float* __restrict__ mask, const float* __restrict__ proto,
    const float* __restrict__ w, const float* __restrict__ pcin,
    float* __restrict__ out)
{
    __shared__ float s_sp[TD];
    __shared__ float s_m[T_];
    __shared__ float s_red[8];
    int bid = blockIdx.x, tid = threadIdx.x;

    // softplus + deterministic sum
    float lsum = 0.f;
    for (int k = tid; k < TD; k += 256) {
        float xv = w[k];
        float sp = fmaxf(xv, 0.f) + log1pf(expf(-fabsf(xv)));  // jax softplus
        s_sp[k] = sp;
        lsum += sp;
    }
    for (int o = 16; o; o >>= 1) lsum += __shfl_xor_sync(0xffffffffu, lsum, o);
    if ((tid & 31) == 0) s_red[tid >> 5] = lsum;
    __syncthreads();
    float tot = 0.f;
    #pragma unroll
    for (int i = 0; i < 8; i++) tot += s_red[i];      // same order everywhere
    float inv = 1.f / tot;

    if (bid < C_) {
        // ---- P' row for class c ----
        int c = bid;
        const float* pr = proto + (size_t)c * TD;
        float* Pr = g_P + (size_t)c * KP;
        const float4* s4 = (const float4*)pr;
        float4* d4 = (float4*)Pr;
        for (int i = tid; i < TD / 4; i += 256) d4[i] = s4[i];
        for (int t = tid; t < T_; t += 256) {
            float q = 0.f;
            #pragma unroll
            for (int d = 0; d < D_; d++) {
                float pv = pr[t * D_ + d];
                q = fmaf(s_sp[t * D_ + d] * pv, pv, q);
            }
            Pr[TD + t] = -0.5f * inv * q;
        }
        for (int k = TD + T_ + tid; k < KP; k += 256) Pr[k] = 0.f;
    } else if (bid < C_ + B_) {
        // ---- Y row + copies + gather for sample b ----
        int b = bid - C_;
        const float* xr = x + (size_t)b * TD;
        const float* mr = mask + (size_t)b * T_;
        float* yr = g_Y + (size_t)b * KP;
        float* oin = out + O_IN + (size_t)b * TD;

        for (int t = tid; t < T_; t += 256) {
            float m = mr[t];
            s_m[t] = m;
            yr[TD + t] = m;
            out[O_MASK + (size_t)b * T_ + t] = m;     // mask pass-through
        }
        __syncthreads();

        float s1 = 0.f;
        for (int k = tid; k < TD; k += 256) {
            float m  = s_m[k / D_];
            float xv = xr[k];
            float y  = m * (s_sp[k] * inv) * xv;
            yr[k] = y;
            oin[k] = xv;                              // input_seq pass-through
            s1 = fmaf(y, xv, s1);
        }
        for (int k = TD + T_ + tid; k < KP; k += 256) yr[k] = 0.f;

        // gather output_seq[b] = prototypes[label[b]]
        int lab = label[b];
        const float4* ps = (const float4*)(proto + (size_t)lab * TD);
        float4* od = (float4*)(out + O_OUT + (size_t)b * TD);
        for (int i = tid; i < TD / 4; i += 256) od[i] = ps[i];
        if (tid == 0) {
            out[O_IDX + b] = (float)lab;              // K=1 -> indices == label
            out[O_LAB + b] = (float)lab;
        }

        // S1 reduce
        for (int o = 16; o; o >>= 1) s1 += __shfl_xor_sync(0xffffffffu, s1, o);
        if ((tid & 31) == 0) s_red[tid >> 5] = s1;
        __syncthreads();
        if (tid == 0) {
            float v = 0.f;
            #pragma unroll
            for (int i = 0; i < 8; i++) v += s_red[i];
            g_S1[b] = v;
        }
    } else {
        // ---- proto_count ----
        __shared__ int cnt[C_];
        if (tid < C_) cnt[tid] = 0;
        __syncthreads();
        atomicAdd(&cnt[label[tid]], 1);               // 256 threads == B_
        __syncthreads();
        if (tid < C_) out[O_PC + tid] = pcin[tid] + (float)cnt[tid];
    }
}

// ---------------------------------------------------------------------------
// Kernel 2: split-K GEMM (packed f32x2) + fused loss epilogue.
// grid = (16 m-tiles of 16 rows, 2 c-tiles of 32, SPLITK). 256 thr = 8 warps.
// Warp grid 2(rows)x4(cols): warp tile 8 rows x 8 cols, lanes split k (4 each).
// Last-finishing z-block per (x,y) tile reduces partials and writes loss.
// ---------------------------------------------------------------------------
__global__ void __launch_bounds__(256) gemm_kernel(float* __restrict__ out) {
    int warp = threadIdx.x >> 5, lane = threadIdx.x & 31;
    int rg = warp & 1, cg = warp >> 1;
    int bmBlk = blockIdx.x * 16;
    int cBlk  = blockIdx.y * 32;
    int bm0 = bmBlk + rg * 8;
    int c0  = cBlk + cg * 8;
    int kz  = blockIdx.z * KCH;

    unsigned long long acc[8][8];
    #pragma unroll
    for (int i = 0; i < 8; i++)
        #pragma unroll
        for (int j = 0; j < 8; j++) acc[i][j] = 0ull;

    const float* Yb = g_Y + (size_t)bm0 * KP;
    const float* Pb = g_P + (size_t)c0 * KP;

    #pragma unroll
    for (int s = 0; s < KCH / 128; s++) {
        int k = kz + s * 128 + lane * 4;
        ulonglong2 pv[8];
        #pragma unroll
        for (int j = 0; j < 8; j++)
            pv[j] = *(const ulonglong2*)(Pb + (size_t)j * KP + k);
        #pragma unroll
        for (int i = 0; i < 8; i++) {
            ulonglong2 yv = *(const ulonglong2*)(Yb + (size_t)i * KP + k);
            #pragma unroll
            for (int j = 0; j < 8; j++) {
                asm("fma.rn.f32x2 %0, %1, %2, %0;"
                    : "+l"(acc[i][j]) : "l"(yv.x), "l"(pv[j].x));
                asm("fma.rn.f32x2 %0, %1, %2, %0;"
                    : "+l"(acc[i][j]) : "l"(yv.y), "l"(pv[j].y));
            }
        }
    }

    float* part = g_part + (size_t)blockIdx.z * B_ * C_;
    #pragma unroll
    for (int i = 0; i < 8; i++) {
        #pragma unroll
        for (int j = 0; j < 8; j++) {
            float2 f = *reinterpret_cast<float2*>(&acc[i][j]);
            float v = f.x + f.y;
            for (int o = 16; o; o >>= 1) v += __shfl_xor_sync(0xffffffffu, v, o);
            if (lane == 0) part[(bm0 + i) * C_ + c0 + j] = v;
        }
    }

    // last-block-done loss epilogue (atomicInc wraps to 0 -> replay-safe)
    __shared__ int s_last;
    __threadfence();
    __syncthreads();
    if (threadIdx.x == 0) {
        unsigned old = atomicInc(&g_cnt[blockIdx.y * 16 + blockIdx.x], SPLITK - 1);
        s_last = (old == SPLITK - 1);
    }
    __syncthreads();
    if (s_last) {
        for (int r = threadIdx.x; r < 512; r += 256) {
            int i = r >> 5, c = r & 31;
            int b = bmBlk + i, cc = cBlk + c;
            float s = 0.f;
            #pragma unroll
            for (int z = 0; z < SPLITK; z++)
                s += __ldcg(&g_part[(z * B_ + b) * C_ + cc]);
            out[O_LOSS + b * C_ + cc] = g_S1[b] - 2.f * s;
        }
    }
}

// ---------------------------------------------------------------------------
extern "C" void kernel_launch(void* const* d_in, const int* in_sizes, int n_in,
                              void* d_out, int out_size) {
    const float* input_seq  = (const float*)d_in[0];
    const int*   label      = (const int*)  d_in[1];
    const float* mask       = (const float*)d_in[2];
    const float* prototypes = (const float*)d_in[3];
    const float* weights    = (const float*)d_in[4];
    const float* protocount = (const float*)d_in[5];
    float* out = (float*)d_out;

    prep_kernel<<<C_ + B_ + 1, 256>>>(input_seq, label, mask, prototypes,
                                      weights, protocount, out);
    gemm_kernel<<<dim3(16, 2, SPLITK), 256>>>(out);
}

// round 4
// speedup vs baseline: 1.1530x; 1.1530x over previous
#include <cuda_runtime.h>
#include <cstdint>

// Problem constants
#define B_  256
#define C_  64
#define T_  406
#define D_  10
#define TD  4060          // T*D
#define KP  4608          // [0,4060)=m*wn*x | [4060,4466)=mask | rest 0
#define ZSPLIT 18
#define ZCH 256           // KP / ZSPLIT
#define STG 64            // k-cols per smem stage
#define MBLK 32
#define LDS_ 68           // smem row stride (68 mod 32 == 4 -> conflict-free frags)

// Output offsets (floats): output_seq, input_seq, loss, indices, label, mask, proto_count
#define O_OUT  0
#define O_IN   1039360
#define O_LOSS 2078720
#define O_IDX  2095104
#define O_LAB  2095360
#define O_MASK 2095616
#define O_PC   2199552

// Static scratch
__device__ __align__(16) float g_Y[B_ * KP];           // 4.72 MB
__device__ __align__(16) float g_P[C_ * KP];           // 1.18 MB
__device__ float g_part[ZSPLIT * B_ * C_];             // 1.18 MB
__device__ float g_S1[B_];
__device__ unsigned g_cnt[8];                           // per M-block arrival counters

__device__ __forceinline__ uint32_t f2tf(float f) {
    uint32_t u;
    asm("cvt.rna.tf32.f32 %0, %1;" : "=r"(u) : "f"(f));
    return u;
}

// ---------------------------------------------------------------------------
// Kernel 1: fused prep (unchanged from R3 — passed).
//   Every block redundantly computes softplus(w)+sum in smem (identical order
//   everywhere -> identical inv). Blocks: [0,64) P' rows, [64,320) Y rows +
//   pass-throughs + gather + idx/label, block 320 proto_count.
// ---------------------------------------------------------------------------
__global__ void __launch_bounds__(256) prep_kernel(
    const float* __restrict__ x, const int* __restrict__ label,
    const float* __restrict__ mask, const float* __restrict__ proto,
    const float* __restrict__ w, const float* __restrict__ pcin,
    float* __restrict__ out)
{
    __shared__ float s_sp[TD];
    __shared__ float s_m[T_];
    __shared__ float s_red[8];
    int bid = blockIdx.x, tid = threadIdx.x;

    float lsum = 0.f;
    for (int k = tid; k < TD; k += 256) {
        float xv = w[k];
        float sp = fmaxf(xv, 0.f) + log1pf(expf(-fabsf(xv)));  // jax softplus
        s_sp[k] = sp;
        lsum += sp;
    }
    for (int o = 16; o; o >>= 1) lsum += __shfl_xor_sync(0xffffffffu, lsum, o);
    if ((tid & 31) == 0) s_red[tid >> 5] = lsum;
    __syncthreads();
    float tot = 0.f;
    #pragma unroll
    for (int i = 0; i < 8; i++) tot += s_red[i];
    float inv = 1.f / tot;

    if (bid < C_) {
        int c = bid;
        const float* pr = proto + (size_t)c * TD;
        float* Pr = g_P + (size_t)c * KP;
        const float4* s4 = (const float4*)pr;
        float4* d4 = (float4*)Pr;
        for (int i = tid; i < TD / 4; i += 256) d4[i] = s4[i];
        for (int t = tid; t < T_; t += 256) {
            float q = 0.f;
            #pragma unroll
            for (int d = 0; d < D_; d++) {
                float pv = pr[t * D_ + d];
                q = fmaf(s_sp[t * D_ + d] * pv, pv, q);
            }
            Pr[TD + t] = -0.5f * inv * q;
        }
        for (int k = TD + T_ + tid; k < KP; k += 256) Pr[k] = 0.f;
    } else if (bid < C_ + B_) {
        int b = bid - C_;
        const float* xr = x + (size_t)b * TD;
        const float* mr = mask + (size_t)b * T_;
        float* yr = g_Y + (size_t)b * KP;
        float* oin = out + O_IN + (size_t)b * TD;

        for (int t = tid; t < T_; t += 256) {
            float m = mr[t];
            s_m[t] = m;
            yr[TD + t] = m;
            out[O_MASK + (size_t)b * T_ + t] = m;
        }
        __syncthreads();

        float s1 = 0.f;
        for (int k = tid; k < TD; k += 256) {
            float m  = s_m[k / D_];
            float xv = xr[k];
            float y  = m * (s_sp[k] * inv) * xv;
            yr[k] = y;
            oin[k] = xv;
            s1 = fmaf(y, xv, s1);
        }
        for (int k = TD + T_ + tid; k < KP; k += 256) yr[k] = 0.f;

        int lab = label[b];
        const float4* ps = (const float4*)(proto + (size_t)lab * TD);
        float4* od = (float4*)(out + O_OUT + (size_t)b * TD);
        for (int i = tid; i < TD / 4; i += 256) od[i] = ps[i];
        if (tid == 0) {
            out[O_IDX + b] = (float)lab;    // K=1 -> indices == label
            out[O_LAB + b] = (float)lab;
        }

        for (int o = 16; o; o >>= 1) s1 += __shfl_xor_sync(0xffffffffu, s1, o);
        if ((tid & 31) == 0) s_red[tid >> 5] = s1;
        __syncthreads();
        if (tid == 0) {
            float v = 0.f;
            #pragma unroll
            for (int i = 0; i < 8; i++) v += s_red[i];
            g_S1[b] = v;
        }
    } else {
        __shared__ int cnt[C_];
        if (tid < C_) cnt[tid] = 0;
        __syncthreads();
        atomicAdd(&cnt[label[tid]], 1);
        __syncthreads();
        if (tid < C_) out[O_PC + tid] = pcin[tid] + (float)cnt[tid];
    }
}

// ---------------------------------------------------------------------------
// Kernel 2: tf32 tensor-core split-K GEMM + fused loss epilogue.
// grid = (8 m-blocks of 32 rows, 18 z). 256 threads = 8 warps (2m x 4n),
// warp tile 16x16 (two m16n8k8 C frags). K chunk 256, staged 4 x 64 cols.
// part[z][b][c] = sum_k Y[b][k]*P[c][k]; last z-block per m-block writes loss.
// ---------------------------------------------------------------------------
__global__ void __launch_bounds__(256) gemm_kernel(float* __restrict__ out) {
    __shared__ uint32_t Ys[MBLK][LDS_];   // 8.7 KB (tf32 bit patterns)
    __shared__ uint32_t Ps[C_][LDS_];     // 17.4 KB
    __shared__ int s_last;

    int tid = threadIdx.x, lane = tid & 31, w = tid >> 5;
    int bm0 = blockIdx.x * MBLK;
    int z = blockIdx.y;
    int kz = z * ZCH;
    int wm = (w & 1) * 16, wn = (w >> 1) * 16;
    int g = lane >> 2, t4 = lane & 3;

    float acc[2][4];
    #pragma unroll
    for (int nf = 0; nf < 2; nf++)
        #pragma unroll
        for (int i = 0; i < 4; i++) acc[nf][i] = 0.f;

    #pragma unroll
    for (int st = 0; st < ZCH / STG; st++) {
        int kb = kz + st * STG;
        // stage Y tile: 32 rows x 64 cols = 512 float4, 2 per thread
        #pragma unroll
        for (int i = 0; i < 2; i++) {
            int idx = tid + i * 256;
            int row = idx >> 4, q = idx & 15;
            float4 v = *(const float4*)&g_Y[(size_t)(bm0 + row) * KP + kb + q * 4];
            uint4 u = { f2tf(v.x), f2tf(v.y), f2tf(v.z), f2tf(v.w) };
            *(uint4*)&Ys[row][q * 4] = u;
        }
        // stage P tile: 64 rows x 64 cols = 1024 float4, 4 per thread
        #pragma unroll
        for (int i = 0; i < 4; i++) {
            int idx = tid + i * 256;
            int row = idx >> 4, q = idx & 15;
            float4 v = *(const float4*)&g_P[(size_t)row * KP + kb + q * 4];
            uint4 u = { f2tf(v.x), f2tf(v.y), f2tf(v.z), f2tf(v.w) };
            *(uint4*)&Ps[row][q * 4] = u;
        }
        __syncthreads();

        #pragma unroll
        for (int kk = 0; kk < STG; kk += 8) {
            uint32_t a0 = Ys[wm + g][kk + t4];
            uint32_t a1 = Ys[wm + g + 8][kk + t4];
            uint32_t a2 = Ys[wm + g][kk + t4 + 4];
            uint32_t a3 = Ys[wm + g + 8][kk + t4 + 4];
            #pragma unroll
            for (int nf = 0; nf < 2; nf++) {
                uint32_t b0 = Ps[wn + nf * 8 + g][kk + t4];
                uint32_t b1 = Ps[wn + nf * 8 + g][kk + t4 + 4];
                asm("mma.sync.aligned.m16n8k8.row.col.f32.tf32.tf32.f32 "
                    "{%0,%1,%2,%3}, {%4,%5,%6,%7}, {%8,%9}, {%0,%1,%2,%3};"
                    : "+f"(acc[nf][0]), "+f"(acc[nf][1]),
                      "+f"(acc[nf][2]), "+f"(acc[nf][3])
                    : "r"(a0), "r"(a1), "r"(a2), "r"(a3), "r"(b0), "r"(b1));
            }
        }
        __syncthreads();
    }

    // write partials: c{0,1} at (row, 2*t4), c{2,3} at (row+8, 2*t4)
    float* part = g_part + (size_t)z * B_ * C_;
    int row = bm0 + wm + g;
    #pragma unroll
    for (int nf = 0; nf < 2; nf++) {
        int col = wn + nf * 8 + 2 * t4;
        *(float2*)&part[row * C_ + col]       = make_float2(acc[nf][0], acc[nf][1]);
        *(float2*)&part[(row + 8) * C_ + col] = make_float2(acc[nf][2], acc[nf][3]);
    }

    // last-z-block-done loss epilogue (atomicInc wraps -> replay-safe)
    __threadfence();
    __syncthreads();
    if (tid == 0) {
        unsigned old = atomicInc(&g_cnt[blockIdx.x], ZSPLIT - 1);
        s_last = (old == ZSPLIT - 1);
    }
    __syncthreads();
    if (s_last) {
        for (int o = tid; o < MBLK * C_; o += 256) {
            int b = bm0 + (o >> 6), c = o & 63;
            float s = 0.f;
            #pragma unroll
            for (int zz = 0; zz < ZSPLIT; zz++)
                s += __ldcg(&g_part[(size_t)zz * B_ * C_ + b * C_ + c]);
            out[O_LOSS + b * C_ + c] = g_S1[b] - 2.f * s;
        }
    }
}

// ---------------------------------------------------------------------------
extern "C" void kernel_launch(void* const* d_in, const int* in_sizes, int n_in,
                              void* d_out, int out_size) {
    const float* input_seq  = (const float*)d_in[0];
    const int*   label      = (const int*)  d_in[1];
    const float* mask       = (const float*)d_in[2];
    const float* prototypes = (const float*)d_in[3];
    const float* weights    = (const float*)d_in[4];
    const float* protocount = (const float*)d_in[5];
    float* out = (float*)d_out;

    prep_kernel<<<C_ + B_ + 1, 256>>>(input_seq, label, mask, prototypes,
                                      weights, protocount, out);
    gemm_kernel<<<dim3(8, ZSPLIT), 256>>>(out);
}

// round 5
// speedup vs baseline: 1.2723x; 1.1035x over previous
#include <cuda_runtime.h>
#include <cstdint>

// Problem constants
#define B_  256
#define C_  64
#define T_  406
#define D_  10
#define TD  4060          // T*D
#define KP  4608          // virtual K: [0,4060)=m*wn*x | [4060,4466)=mask | rest 0
#define ZSPLIT 18
#define ZCH 256           // KP / ZSPLIT
#define STG 64            // k-cols per smem stage
#define MBLK 32
#define LDS_ 68           // smem row stride (pad -> conflict-free frags)

// Output offsets (floats): output_seq, input_seq, loss, indices, label, mask, proto_count
#define O_OUT  0
#define O_IN   1039360
#define O_LOSS 2078720
#define O_IDX  2095104
#define O_LAB  2095360
#define O_MASK 2095616
#define O_PC   2199552

// Static scratch
__device__ __align__(16) float g_wn[4060];             // normalized softplus weights
__device__ __align__(16) float g_P[C_ * KP];           // 1.18 MB  (P' rows)
__device__ float g_part[ZSPLIT * B_ * C_];             // 1.18 MB  (GEMM partials)
__device__ float g_S1part[ZSPLIT * B_];                // S1 partials per z
__device__ unsigned g_cnt[8];                           // per M-block arrival counters

__device__ __forceinline__ uint32_t f2tf(float f) {
    uint32_t u;
    asm("cvt.rna.tf32.f32 %0, %1;" : "=r"(u) : "f"(f));
    return u;
}

// ---------------------------------------------------------------------------
// Kernel 1: prep.
//   blocks [0,64):  softplus (redundant, identical order) -> P' row c
//   blocks [64,320): pure data movement: input/mask pass-through, prototype
//                    gather, indices/label (no softplus needed)
//   block 320:      softplus -> write normalized g_wn; proto_count
// ---------------------------------------------------------------------------
__global__ void __launch_bounds__(256) prep_kernel(
    const float* __restrict__ x, const int* __restrict__ label,
    const float* __restrict__ mask, const float* __restrict__ proto,
    const float* __restrict__ w, const float* __restrict__ pcin,
    float* __restrict__ out)
{
    __shared__ float s_sp[TD];
    __shared__ float s_red[8];
    __shared__ int s_cnt[C_];
    int bid = blockIdx.x, tid = threadIdx.x;

    if (bid < C_ || bid == C_ + B_) {
        // softplus + deterministic sum (identical in every block that runs it)
        float lsum = 0.f;
        for (int k = tid; k < TD; k += 256) {
            float xv = w[k];
            float sp = fmaxf(xv, 0.f) + log1pf(expf(-fabsf(xv)));  // jax softplus
            s_sp[k] = sp;
            lsum += sp;
        }
        for (int o = 16; o; o >>= 1) lsum += __shfl_xor_sync(0xffffffffu, lsum, o);
        if ((tid & 31) == 0) s_red[tid >> 5] = lsum;
        __syncthreads();
        float tot = 0.f;
        #pragma unroll
        for (int i = 0; i < 8; i++) tot += s_red[i];
        float inv = 1.f / tot;

        if (bid < C_) {
            // ---- P' row for class c = [p | -0.5*inv*Q | 0] ----
            int c = bid;
            const float* pr = proto + (size_t)c * TD;
            float* Pr = g_P + (size_t)c * KP;
            const float4* s4 = (const float4*)pr;
            float4* d4 = (float4*)Pr;
            for (int i = tid; i < TD / 4; i += 256) d4[i] = s4[i];
            for (int t = tid; t < T_; t += 256) {
                float q = 0.f;
                #pragma unroll
                for (int d = 0; d < D_; d++) {
                    float pv = pr[t * D_ + d];
                    q = fmaf(s_sp[t * D_ + d] * pv, pv, q);
                }
                Pr[TD + t] = -0.5f * inv * q;
            }
            for (int k = TD + T_ + tid; k < KP; k += 256) Pr[k] = 0.f;
        } else {
            // ---- g_wn + proto_count ----
            for (int k = tid; k < TD; k += 256) g_wn[k] = s_sp[k] * inv;
            if (tid < C_) s_cnt[tid] = 0;
            __syncthreads();
            atomicAdd(&s_cnt[label[tid]], 1);          // 256 threads == B_
            __syncthreads();
            if (tid < C_) out[O_PC + tid] = pcin[tid] + (float)s_cnt[tid];
        }
    } else {
        // ---- pure copies for sample b ----
        int b = bid - C_;
        const float4* xs = (const float4*)(x + (size_t)b * TD);
        float4* oin = (float4*)(out + O_IN + (size_t)b * TD);
        for (int i = tid; i < TD / 4; i += 256) oin[i] = xs[i];
        for (int t = tid; t < T_; t += 256)
            out[O_MASK + (size_t)b * T_ + t] = mask[(size_t)b * T_ + t];

        int lab = label[b];
        const float4* ps = (const float4*)(proto + (size_t)lab * TD);
        float4* od = (float4*)(out + O_OUT + (size_t)b * TD);
        for (int i = tid; i < TD / 4; i += 256) od[i] = ps[i];
        if (tid == 0) {
            out[O_IDX + b] = (float)lab;               // K=1 -> indices == label
            out[O_LAB + b] = (float)lab;
        }
    }
}

// ---------------------------------------------------------------------------
// Kernel 2: tf32 tensor-core split-K GEMM, Y built on the fly, software-
// pipelined staging, S1 computed in-staging, fused loss epilogue.
// grid = (8 m-blocks of 32 rows, 18 z). 256 threads = 8 warps (2m x 4n).
// ---------------------------------------------------------------------------
__global__ void __launch_bounds__(256) gemm_kernel(
    const float* __restrict__ x, const float* __restrict__ mask,
    float* __restrict__ out)
{
    __shared__ uint32_t Ys[MBLK][LDS_];   // tf32 bit patterns
    __shared__ uint32_t Ps[C_][LDS_];
    __shared__ int s_last;

    int tid = threadIdx.x, lane = tid & 31, w = tid >> 5;
    int bm0 = blockIdx.x * MBLK;
    int z = blockIdx.y, kz = z * ZCH;
    int wm = (w & 1) * 16, wn = (w >> 1) * 16;
    int g = lane >> 2, t4 = lane & 3;
    int srow = tid >> 4, sq = tid & 15;   // staging row (0..15) / quad (0..15)

    float acc[2][4];
    #pragma unroll
    for (int nf = 0; nf < 2; nf++)
        #pragma unroll
        for (int i = 0; i < 4; i++) acc[nf][i] = 0.f;
    float s1a[2] = {0.f, 0.f};

    // prefetch registers for one stage
    float4 xv[2], pv[4];
    float wnv[2][4], mv[2][4];
    int cur_k0 = 0;

    auto load_stage = [&](int st) {
        int k0 = kz + st * STG + sq * 4;
        cur_k0 = k0;
        #pragma unroll
        for (int i = 0; i < 2; i++) {
            int r = bm0 + srow + i * 16;
            if (k0 < TD) {
                xv[i] = *(const float4*)&x[(size_t)r * TD + k0];
                float4 wq = *(const float4*)&g_wn[k0];
                wnv[i][0] = wq.x; wnv[i][1] = wq.y;
                wnv[i][2] = wq.z; wnv[i][3] = wq.w;
                #pragma unroll
                for (int j = 0; j < 4; j++) {
                    int t = (k0 + j) / D_;
                    mv[i][j] = __ldg(&mask[(size_t)r * T_ + t]);
                }
            } else {
                #pragma unroll
                for (int j = 0; j < 4; j++) {
                    int k = k0 + j;
                    mv[i][j] = (k < TD + T_) ? __ldg(&mask[(size_t)r * T_ + (k - TD)])
                                             : 0.f;
                }
            }
        }
        #pragma unroll
        for (int i = 0; i < 4; i++)
            pv[i] = *(const float4*)&g_P[(size_t)(srow + i * 16) * KP + k0];
    };

    auto store_stage = [&]() {
        #pragma unroll
        for (int i = 0; i < 2; i++) {
            float y[4];
            if (cur_k0 < TD) {
                float xx[4] = { xv[i].x, xv[i].y, xv[i].z, xv[i].w };
                #pragma unroll
                for (int j = 0; j < 4; j++) {
                    y[j] = mv[i][j] * wnv[i][j] * xx[j];
                    s1a[i] = fmaf(y[j], xx[j], s1a[i]);
                }
            } else {
                #pragma unroll
                for (int j = 0; j < 4; j++) y[j] = mv[i][j];
            }
            uint4 u = { f2tf(y[0]), f2tf(y[1]), f2tf(y[2]), f2tf(y[3]) };
            *(uint4*)&Ys[srow + i * 16][sq * 4] = u;
        }
        #pragma unroll
        for (int i = 0; i < 4; i++) {
            uint4 u = { f2tf(pv[i].x), f2tf(pv[i].y), f2tf(pv[i].z), f2tf(pv[i].w) };
            *(uint4*)&Ps[srow + i * 16][sq * 4] = u;
        }
    };

    load_stage(0);
    #pragma unroll
    for (int st = 0; st < ZCH / STG; st++) {
        store_stage();
        __syncthreads();
        if (st < ZCH / STG - 1) load_stage(st + 1);   // overlaps with mma below
        #pragma unroll
        for (int kk = 0; kk < STG; kk += 8) {
            uint32_t a0 = Ys[wm + g][kk + t4];
            uint32_t a1 = Ys[wm + g + 8][kk + t4];
            uint32_t a2 = Ys[wm + g][kk + t4 + 4];
            uint32_t a3 = Ys[wm + g + 8][kk + t4 + 4];
            #pragma unroll
            for (int nf = 0; nf < 2; nf++) {
                uint32_t b0 = Ps[wn + nf * 8 + g][kk + t4];
                uint32_t b1 = Ps[wn + nf * 8 + g][kk + t4 + 4];
                asm("mma.sync.aligned.m16n8k8.row.col.f32.tf32.tf32.f32 "
                    "{%0,%1,%2,%3}, {%4,%5,%6,%7}, {%8,%9}, {%0,%1,%2,%3};"
                    : "+f"(acc[nf][0]), "+f"(acc[nf][1]),
                      "+f"(acc[nf][2]), "+f"(acc[nf][3])
                    : "r"(a0), "r"(a1), "r"(a2), "r"(a3), "r"(b0), "r"(b1));
            }
        }
        __syncthreads();
    }

    // GEMM partials
    float* part = g_part + (size_t)z * B_ * C_;
    int orow = bm0 + wm + g;
    #pragma unroll
    for (int nf = 0; nf < 2; nf++) {
        int col = wn + nf * 8 + 2 * t4;
        *(float2*)&part[orow * C_ + col]       = make_float2(acc[nf][0], acc[nf][1]);
        *(float2*)&part[(orow + 8) * C_ + col] = make_float2(acc[nf][2], acc[nf][3]);
    }

    // S1 partials: reduce over the 16 staging threads of each row (deterministic)
    #pragma unroll
    for (int i = 0; i < 2; i++) {
        float v = s1a[i];
        #pragma unroll
        for (int o = 8; o; o >>= 1) v += __shfl_xor_sync(0xffffffffu, v, o);
        if ((lane & 15) == 0) g_S1part[z * B_ + bm0 + srow + i * 16] = v;
    }

    // last-z-block-done loss epilogue (atomicInc wraps -> replay-safe)
    __threadfence();
    __syncthreads();
    if (tid == 0) {
        unsigned old = atomicInc(&g_cnt[blockIdx.x], ZSPLIT - 1);
        s_last = (old == ZSPLIT - 1);
    }
    __syncthreads();
    if (s_last) {
        for (int o = tid; o < MBLK * C_; o += 256) {
            int b = bm0 + (o >> 6), c = o & 63;
            float s = 0.f, s1 = 0.f;
            #pragma unroll
            for (int zz = 0; zz < ZSPLIT; zz++) {
                s  += __ldcg(&g_part[(size_t)zz * B_ * C_ + b * C_ + c]);
                s1 += __ldcg(&g_S1part[zz * B_ + b]);
            }
            out[O_LOSS + b * C_ + c] = s1 - 2.f * s;
        }
    }
}

// ---------------------------------------------------------------------------
extern "C" void kernel_launch(void* const* d_in, const int* in_sizes, int n_in,
                              void* d_out, int out_size) {
    const float* input_seq  = (const float*)d_in[0];
    const int*   label      = (const int*)  d_in[1];
    const float* mask       = (const float*)d_in[2];
    const float* prototypes = (const float*)d_in[3];
    const float* weights    = (const float*)d_in[4];
    const float* protocount = (const float*)d_in[5];
    float* out = (float*)d_out;

    prep_kernel<<<C_ + B_ + 1, 256>>>(input_seq, label, mask, prototypes,
                                      weights, protocount, out);
    gemm_kernel<<<dim3(8, ZSPLIT), 256>>>(input_seq, mask, out);
}